// round 1
// baseline (speedup 1.0000x reference)
#include <cuda_runtime.h>
#include <math.h>

// Problem constants
#define HH 8
#define BB 8
#define LL 2048
#define MM 1024
#define DD 64
// N per head = BB*LL = 16384

// Output layout (fp32, concatenated in reference return order)
#define OFF_ZQ   0
#define N_ZQ     (8*512*2048)            // 8,388,608
#define OFF_LOSS (N_ZQ)                  // 8,388,608
#define OFF_IDX  (N_ZQ + 1)              // 8,388,609
#define N_IDX    (BB*HH*LL)              // 131,072
#define OFF_CB   (OFF_IDX + N_IDX)       // 8,519,681

#define RMS_EPS  1.1920929e-07f
#define COS_EPS  1e-8f

// Scratch (device globals, no allocation)
__device__ float g_sums[HH*MM*DD];   // segment sums of z per code
__device__ float g_counts[HH*MM];
__device__ float g_loss;

// ---------------------------------------------------------------------------
// Kernel 0: zero scratch (graph-replay safe)
// ---------------------------------------------------------------------------
__global__ void vq_zero() {
    int i = blockIdx.x * blockDim.x + threadIdx.x;
    int stride = gridDim.x * blockDim.x;
    for (int j = i; j < HH*MM*DD; j += stride) g_sums[j] = 0.0f;
    if (i < HH*MM) g_counts[i] = 0.0f;
    if (i == 0) g_loss = 0.0f;
}

// ---------------------------------------------------------------------------
// Kernel 1: fused sim-GEMM + argmax + z_q gather + loss + segment sums
// Block: 256 threads = 16(ty, row-groups) x 16(tx, m-groups)
// Each block: one (b, h), 64 consecutive l values, all M=1024 codes.
// ---------------------------------------------------------------------------
__global__ __launch_bounds__(256)
void vq_main(const float* __restrict__ z, const float* __restrict__ cb,
             float* __restrict__ out) {
    const int lt = blockIdx.x;          // 0..31  (l tile)
    const int h  = blockIdx.y;          // 0..7
    const int b  = blockIdx.z;          // 0..7
    const int l0 = lt * 64;

    __shared__ float zsh[64][68];       // [l][k], pad to 68 floats
    __shared__ float csh[64][68];       // [m within tile][k]
    __shared__ int   sidx[64];
    __shared__ float wsum[8];

    const int tid = threadIdx.x;
    const int ty = tid >> 4;            // 0..15 row group
    const int tx = tid & 15;            // 0..15 m group

    // Load z tile: z[b, h*64+k, l0+l]  (coalesced over l)
    const float* zbase = z + ((size_t)b * 512 + (size_t)h * 64) * 2048 + l0;
    for (int i = tid; i < 64 * 64; i += 256) {
        int k = i >> 6, l = i & 63;
        zsh[l][k] = zbase[(size_t)k * 2048 + l];
    }
    __syncthreads();

    const float* cbh = cb + (size_t)h * MM * DD;

    float best[4];
    int   bidx[4];
#pragma unroll
    for (int i = 0; i < 4; i++) { best[i] = -1e30f; bidx[i] = 0; }

    const int r0 = ty * 4;
    const int c0 = tx * 4;

    for (int mt = 0; mt < MM; mt += 64) {
        // Load 64x64 codebook tile (coalesced rows)
        for (int i = tid; i < 64 * 64; i += 256) {
            int mm = i >> 6, k = i & 63;
            csh[mm][k] = cbh[(size_t)(mt + mm) * DD + k];
        }
        __syncthreads();

        float acc[4][4];
#pragma unroll
        for (int i = 0; i < 4; i++)
#pragma unroll
            for (int j = 0; j < 4; j++) acc[i][j] = 0.0f;

#pragma unroll
        for (int k4 = 0; k4 < 16; k4++) {
            float4 zv[4], cv[4];
#pragma unroll
            for (int i = 0; i < 4; i++)
                zv[i] = *(const float4*)&zsh[r0 + i][k4 * 4];
#pragma unroll
            for (int j = 0; j < 4; j++)
                cv[j] = *(const float4*)&csh[c0 + j][k4 * 4];
#pragma unroll
            for (int i = 0; i < 4; i++)
#pragma unroll
                for (int j = 0; j < 4; j++) {
                    acc[i][j] = fmaf(zv[i].x, cv[j].x, acc[i][j]);
                    acc[i][j] = fmaf(zv[i].y, cv[j].y, acc[i][j]);
                    acc[i][j] = fmaf(zv[i].z, cv[j].z, acc[i][j]);
                    acc[i][j] = fmaf(zv[i].w, cv[j].w, acc[i][j]);
                }
        }

        // Local argmax update (lowest index wins ties)
#pragma unroll
        for (int i = 0; i < 4; i++)
#pragma unroll
            for (int j = 0; j < 4; j++) {
                int mi = mt + c0 + j;
                float v = acc[i][j];
                if (v > best[i] || (v == best[i] && mi < bidx[i])) {
                    best[i] = v; bidx[i] = mi;
                }
            }
        __syncthreads();
    }

    // Cross-lane argmax reduce over the 16 tx lanes sharing each row group.
    // tid = ty*16+tx -> the 16 threads of a ty group are contiguous lanes.
#pragma unroll
    for (int off = 8; off > 0; off >>= 1) {
#pragma unroll
        for (int i = 0; i < 4; i++) {
            float ov = __shfl_xor_sync(0xFFFFFFFFu, best[i], off);
            int   oi = __shfl_xor_sync(0xFFFFFFFFu, bidx[i], off);
            if (ov > best[i] || (ov == best[i] && oi < bidx[i])) {
                best[i] = ov; bidx[i] = oi;
            }
        }
    }

    if (tx < 4) {
        int l = r0 + tx;            // row handled by this lane
        int m = bidx[tx];
        sidx[l] = m;
        out[OFF_IDX + ((size_t)(b * HH + h)) * LL + l0 + l] = (float)m;
        atomicAdd(&g_counts[h * MM + m], 1.0f);
    }
    __syncthreads();

    // Cooperative epilogue: z_q write (coalesced over l), loss, segment sums
    float lsum = 0.0f;
    for (int i = tid; i < 64 * 64; i += 256) {
        int k = i >> 6, l = i & 63;
        int m = sidx[l];
        float cv = __ldg(&cbh[(size_t)m * DD + k]);
        float zv = zsh[l][k];
        float dd = zv - cv;
        lsum += dd * dd;
        out[OFF_ZQ + ((size_t)b * 512 + (size_t)h * 64 + k) * 2048 + l0 + l] = cv;
        atomicAdd(&g_sums[((size_t)(h * MM + m)) * DD + k], zv);
    }

    // Block-reduce loss
#pragma unroll
    for (int off = 16; off > 0; off >>= 1)
        lsum += __shfl_xor_sync(0xFFFFFFFFu, lsum, off);
    int warp = tid >> 5, lane = tid & 31;
    if (lane == 0) wsum[warp] = lsum;
    __syncthreads();
    if (tid == 0) {
        float s = 0.0f;
#pragma unroll
        for (int w = 0; w < 8; w++) s += wsum[w];
        atomicAdd(&g_loss, s);
    }
}

// ---------------------------------------------------------------------------
// Kernel 2: EMA slerp codebook update + loss finalize. One warp per (h, m).
// Lanes hold elements k = lane and k = lane+32.
// ---------------------------------------------------------------------------
__global__ __launch_bounds__(256)
void vq_update(const float* __restrict__ cb, float* __restrict__ out) {
    int gid = blockIdx.x * blockDim.x + threadIdx.x;
    int gw = gid >> 5;
    int lane = threadIdx.x & 31;

    if (gw == 0 && lane == 0)
        out[OFF_LOSS] = 1.25f * g_loss / 8388608.0f;  // mean over H*N*d

    if (gw >= HH * MM) return;
    int h = gw >> 10;
    int m = gw & (MM - 1);

    const float* hi = cb + ((size_t)h * MM + m) * DD;
    float h0 = hi[lane], h1 = hi[lane + 32];
    float cnt = g_counts[h * MM + m];
    float o0 = h0, o1 = h1;

    if (cnt > 0.0f) {
        float inv = 1.0f / fmaxf(cnt, 1.0f);
        const float* sp = g_sums + ((size_t)h * MM + m) * DD;
        float s0 = sp[lane] * inv, s1 = sp[lane + 32] * inv;  // means (low)

        float dot = s0 * h0 + s1 * h1;
        float nl = s0 * s0 + s1 * s1;
        float nh = h0 * h0 + h1 * h1;
#pragma unroll
        for (int off = 16; off > 0; off >>= 1) {
            dot += __shfl_xor_sync(0xFFFFFFFFu, dot, off);
            nl  += __shfl_xor_sync(0xFFFFFFFFu, nl, off);
            nh  += __shfl_xor_sync(0xFFFFFFFFu, nh, off);
        }
        float c = dot / fmaxf(sqrtf(nl) * sqrtf(nh), COS_EPS);
        c = fminf(fmaxf(c, -1.0f + 1e-7f), 1.0f - 1e-7f);
        float om = acosf(c);
        float so = sinf(om);
        float wl = sinf(0.01f * om) / so;   // weight on low (means), val=0.99
        float wh = sinf(0.99f * om) / so;   // weight on high (codebooks)
        float r0 = s0 * wl + h0 * wh;
        float r1 = s1 * wl + h1 * wh;

        float ms = r0 * r0 + r1 * r1;
#pragma unroll
        for (int off = 16; off > 0; off >>= 1)
            ms += __shfl_xor_sync(0xFFFFFFFFu, ms, off);
        float rinv = rsqrtf(ms * (1.0f / 64.0f) + RMS_EPS);
        o0 = r0 * rinv;
        o1 = r1 * rinv;
    }

    size_t ob = OFF_CB + ((size_t)h * MM + m) * DD;
    out[ob + lane] = o0;
    out[ob + lane + 32] = o1;
}

// ---------------------------------------------------------------------------
extern "C" void kernel_launch(void* const* d_in, const int* in_sizes, int n_in,
                              void* d_out, int out_size) {
    const float* z  = (const float*)d_in[0];         // [8, 512, 2048]
    const float* cb = (const float*)d_in[1];         // [8, 1024, 64]
    float* out = (float*)d_out;

    vq_zero<<<512, 256>>>();
    dim3 grid(32, HH, BB);
    vq_main<<<grid, 256>>>(z, cb, out);
    vq_update<<<HH * MM * 32 / 256, 256>>>(cb, out);
}

// round 3
// speedup vs baseline: 2.5092x; 2.5092x over previous
#include <cuda_runtime.h>
#include <cuda_bf16.h>
#include <math.h>
#include <cstdint>

// ---------------- problem constants ----------------
#define HH 8
#define BB 8
#define LL 2048
#define MM 1024
#define DD 64
#define NPH 16384                         // tokens per head = BB*LL

// output layout (fp32, reference return order)
#define OFF_ZQ   0
#define N_ZQ     (8*512*2048)             // 8,388,608
#define OFF_LOSS (N_ZQ)
#define OFF_IDX  (N_ZQ + 1)
#define OFF_CB   (OFF_IDX + BB*HH*LL)

#define RMS_EPS  1.1920929e-07f
#define COS_EPS  1e-8f

// ---------------- device scratch (no allocs) ----------------
__device__ __align__(128) __nv_bfloat16 g_z1[HH*NPH*DD];
__device__ __align__(128) __nv_bfloat16 g_z2[HH*NPH*DD];
__device__ __align__(128) __nv_bfloat16 g_z3[HH*NPH*DD];
__device__ __align__(128) __nv_bfloat16 g_c1[HH*MM*DD];
__device__ __align__(128) __nv_bfloat16 g_c2[HH*MM*DD];
__device__ __align__(128) __nv_bfloat16 g_c3[HH*MM*DD];
__device__ int   g_idx[HH*NPH];
__device__ __align__(16) float g_sums[HH*MM*DD];
__device__ float g_counts[HH*MM];
__device__ float g_loss;

// ---------------------------------------------------------------------------
// warp mma: D = A(16x16 bf16, row) * B(16x8 bf16, col) + C   (fp32 accum)
// ---------------------------------------------------------------------------
__device__ __forceinline__ void mma_bf16(float* d, const uint32_t* a,
                                         const uint32_t* b) {
    asm volatile(
        "mma.sync.aligned.m16n8k16.row.col.f32.bf16.bf16.f32 "
        "{%0,%1,%2,%3}, {%4,%5,%6,%7}, {%8,%9}, {%0,%1,%2,%3};"
        : "+f"(d[0]), "+f"(d[1]), "+f"(d[2]), "+f"(d[3])
        : "r"(a[0]), "r"(a[1]), "r"(a[2]), "r"(a[3]), "r"(b[0]), "r"(b[1]));
}

// ---------------------------------------------------------------------------
// split fp32 -> 3 bf16 terms
// ---------------------------------------------------------------------------
__device__ __forceinline__ void split3(float v, __nv_bfloat16& a, __nv_bfloat16& b,
                                       __nv_bfloat16& c) {
    a = __float2bfloat16(v);
    float r = v - __bfloat162float(a);
    b = __float2bfloat16(r);
    float r2 = r - __bfloat162float(b);
    c = __float2bfloat16(r2);
}

// ---------------------------------------------------------------------------
// K0: prep — z transpose+split to [h][n][d] bf16 triples; cb split; zero scratch
// ---------------------------------------------------------------------------
__global__ __launch_bounds__(256)
void vq_prep(const float* __restrict__ z, const float* __restrict__ cb) {
    __shared__ float zsh[64][65];
    const int x = blockIdx.x, tid = threadIdx.x;
    if (x < 2048) {
        const int b = x >> 8, h = (x >> 5) & 7, lt = x & 31, l0 = lt * 64;
        const float* zb = z + ((size_t)b * 512 + (size_t)h * 64) * 2048 + l0;
        for (int i = tid; i < 4096; i += 256) {
            int k = i >> 6, l = i & 63;
            zsh[k][l] = zb[(size_t)k * 2048 + l];
        }
        __syncthreads();
        for (int i = tid; i < 2048; i += 256) {
            int l = i >> 5, u = i & 31;
            float v0 = zsh[2 * u][l], v1 = zsh[2 * u + 1][l];
            __nv_bfloat16 a0, b0, c0, a1, b1, c1;
            split3(v0, a0, b0, c0);
            split3(v1, a1, b1, c1);
            size_t row = (size_t)h * NPH + (size_t)b * 2048 + l0 + l;
            size_t off = row * 32 + u;
            __nv_bfloat162 t;
            t.x = a0; t.y = a1; ((__nv_bfloat162*)g_z1)[off] = t;
            t.x = b0; t.y = b1; ((__nv_bfloat162*)g_z2)[off] = t;
            t.x = c0; t.y = c1; ((__nv_bfloat162*)g_z3)[off] = t;
        }
    } else {
        int i = (x - 2048) * 256 + tid;   // < 524288
        float v = cb[i];
        __nv_bfloat16 a, b, c;
        split3(v, a, b, c);
        g_c1[i] = a; g_c2[i] = b; g_c3[i] = c;
        g_sums[i] = 0.0f;
        if (i < HH * MM) g_counts[i] = 0.0f;
        if (i == 0) g_loss = 0.0f;
    }
}

// ---------------------------------------------------------------------------
// K1: HMMA 6-pair bf16 sim-GEMM + fused argmax.
// CTA = (head, 128 tokens). 8 warps; warp w owns rows [w*16, w*16+16).
// B (codebook) tiled 128 cols at a time through smem (144B pitch, conflict-free).
// ---------------------------------------------------------------------------
#define BPITCH 144
#define BTERM  (128 * BPITCH)     // 18432 bytes per term
#define SM_GEMM (3 * BTERM)       // 55296

__global__ __launch_bounds__(256)
void vq_gemm(float* __restrict__ out) {
    extern __shared__ char bsh[];
    const int h  = blockIdx.y;
    const int n0 = blockIdx.x * 128;
    const int tid = threadIdx.x;
    const int w = tid >> 5, l = tid & 31;
    const int gq = l >> 2, tq = l & 3;

    // ---- preload A fragments (3 terms x 4 ksteps x 4 regs) from global ----
    uint32_t afr[3][4][4];
    {
        const size_t r0 = (size_t)h * NPH + n0 + w * 16 + gq;   // row for a0/a2
#pragma unroll
        for (int t3 = 0; t3 < 3; t3++) {
            const __nv_bfloat16* zp = (t3 == 0) ? g_z1 : (t3 == 1) ? g_z2 : g_z3;
            const char* base0 = (const char*)(zp + r0 * DD) + 4 * tq;
            const char* base1 = base0 + 8 * DD * 2;             // row +8
#pragma unroll
            for (int ks = 0; ks < 4; ks++) {
                afr[t3][ks][0] = __ldg((const uint32_t*)(base0 + ks * 32));
                afr[t3][ks][1] = __ldg((const uint32_t*)(base1 + ks * 32));
                afr[t3][ks][2] = __ldg((const uint32_t*)(base0 + ks * 32 + 16));
                afr[t3][ks][3] = __ldg((const uint32_t*)(base1 + ks * 32 + 16));
            }
        }
    }

    float best0 = -3.0e38f, best1 = -3.0e38f;
    int   bidx0 = 0, bidx1 = 0;

    const int PA[6] = {0, 0, 1, 0, 1, 2};
    const int PB[6] = {0, 1, 0, 2, 1, 0};

    for (int mt = 0; mt < 8; mt++) {
        __syncthreads();
        // ---- stage B tile: 128 codes x 64 k x 3 terms, pitch 144B ----
#pragma unroll
        for (int t3 = 0; t3 < 3; t3++) {
            const __nv_bfloat16* cp = (t3 == 0) ? g_c1 : (t3 == 1) ? g_c2 : g_c3;
            const uint4* src = (const uint4*)(cp + ((size_t)h * MM + mt * 128) * DD);
            char* dst = bsh + t3 * BTERM;
            for (int i = tid; i < 1024; i += 256) {
                int r = i >> 3, c = i & 7;
                *(uint4*)(dst + r * BPITCH + c * 16) = __ldg(src + i);
            }
        }
        __syncthreads();

#pragma unroll
        for (int sg = 0; sg < 4; sg++) {
            float acc[4][4];
#pragma unroll
            for (int s = 0; s < 4; s++)
#pragma unroll
                for (int i = 0; i < 4; i++) acc[s][i] = 0.0f;

#pragma unroll
            for (int ks = 0; ks < 4; ks++) {
                uint32_t bf[4][3][2];
#pragma unroll
                for (int s = 0; s < 4; s++) {
                    const char* p = bsh + (sg * 32 + s * 8 + gq) * BPITCH
                                        + ks * 32 + 4 * tq;
#pragma unroll
                    for (int t3 = 0; t3 < 3; t3++) {
                        bf[s][t3][0] = *(const uint32_t*)(p + t3 * BTERM);
                        bf[s][t3][1] = *(const uint32_t*)(p + t3 * BTERM + 16);
                    }
                }
#pragma unroll
                for (int p6 = 0; p6 < 6; p6++)
#pragma unroll
                    for (int s = 0; s < 4; s++)
                        mma_bf16(acc[s], afr[PA[p6]][ks], bf[s][PB[p6]]);
            }

            // argmax update (strict > keeps lowest index on ties)
#pragma unroll
            for (int s = 0; s < 4; s++) {
                int nb = mt * 128 + sg * 32 + s * 8 + 2 * tq;
                if (acc[s][0] > best0) { best0 = acc[s][0]; bidx0 = nb; }
                if (acc[s][1] > best0) { best0 = acc[s][1]; bidx0 = nb + 1; }
                if (acc[s][2] > best1) { best1 = acc[s][2]; bidx1 = nb; }
                if (acc[s][3] > best1) { best1 = acc[s][3]; bidx1 = nb + 1; }
            }
        }
    }

    // ---- reduce across the 4 lanes covering each row ----
#pragma unroll
    for (int off = 1; off <= 2; off <<= 1) {
        float ov = __shfl_xor_sync(0xFFFFFFFFu, best0, off);
        int   oi = __shfl_xor_sync(0xFFFFFFFFu, bidx0, off);
        if (ov > best0 || (ov == best0 && oi < bidx0)) { best0 = ov; bidx0 = oi; }
        ov = __shfl_xor_sync(0xFFFFFFFFu, best1, off);
        oi = __shfl_xor_sync(0xFFFFFFFFu, bidx1, off);
        if (ov > best1 || (ov == best1 && oi < bidx1)) { best1 = ov; bidx1 = oi; }
    }

    if (tq == 0) {
        int n = n0 + w * 16 + gq;          // row for best0; best1 is n+8
        g_idx[h * NPH + n] = bidx0;
        g_idx[h * NPH + n + 8] = bidx1;
        int b = n >> 11, ll = n & 2047;
        out[OFF_IDX + ((size_t)(b * HH + h)) * LL + ll] = (float)bidx0;
        int n2 = n + 8;
        int b2 = n2 >> 11, ll2 = n2 & 2047;
        out[OFF_IDX + ((size_t)(b2 * HH + h)) * LL + ll2] = (float)bidx1;
    }
}

// ---------------------------------------------------------------------------
// K2: epilogue — z_q gather, loss, counts, segment sums (float4 vector atomics)
// ---------------------------------------------------------------------------
__global__ __launch_bounds__(256)
void vq_epi(const float* __restrict__ z, const float* __restrict__ cb,
            float* __restrict__ out) {
    const int lt = blockIdx.x, h = blockIdx.y, b = blockIdx.z;
    const int l0 = lt * 64;
    __shared__ float zsh[64][65];
    __shared__ int sidx[64];
    __shared__ float wsum[8];
    const int tid = threadIdx.x;

    const float* zb = z + ((size_t)b * 512 + (size_t)h * 64) * 2048 + l0;
    for (int i = tid; i < 4096; i += 256) {
        int k = i >> 6, l = i & 63;
        zsh[k][l] = zb[(size_t)k * 2048 + l];
    }
    if (tid < 64) {
        int m = g_idx[h * NPH + b * 2048 + l0 + tid];
        sidx[tid] = m;
        atomicAdd(&g_counts[h * MM + m], 1.0f);
    }
    __syncthreads();

    const float* cbh = cb + (size_t)h * MM * DD;
    float lsum = 0.0f;
    for (int i = tid; i < 4096; i += 256) {
        int k = i >> 6, l = i & 63;
        int m = sidx[l];
        float cv = __ldg(&cbh[(size_t)m * DD + k]);
        float zv = zsh[k][l];
        float d = zv - cv;
        lsum += d * d;
        out[OFF_ZQ + ((size_t)b * 512 + (size_t)h * 64 + k) * 2048 + l0 + l] = cv;
    }

    // segment sums: thread = (l, 4k-group) -> float4 atomic
    for (int i = tid; i < 1024; i += 256) {
        int l = i >> 4, kg = i & 15;
        int m = sidx[l];
        float4 v = make_float4(zsh[4 * kg][l], zsh[4 * kg + 1][l],
                               zsh[4 * kg + 2][l], zsh[4 * kg + 3][l]);
        atomicAdd((float4*)&g_sums[((size_t)(h * MM + m)) * DD + 4 * kg], v);
    }

    // loss reduce
#pragma unroll
    for (int off = 16; off > 0; off >>= 1)
        lsum += __shfl_xor_sync(0xFFFFFFFFu, lsum, off);
    int warp = tid >> 5, lane = tid & 31;
    if (lane == 0) wsum[warp] = lsum;
    __syncthreads();
    if (tid == 0) {
        float s = 0.0f;
#pragma unroll
        for (int w = 0; w < 8; w++) s += wsum[w];
        atomicAdd(&g_loss, s);
    }
}

// ---------------------------------------------------------------------------
// K3: EMA slerp codebook update + loss finalize. One warp per (h, m).
// ---------------------------------------------------------------------------
__global__ __launch_bounds__(256)
void vq_update(const float* __restrict__ cb, float* __restrict__ out) {
    int gid = blockIdx.x * blockDim.x + threadIdx.x;
    int gw = gid >> 5;
    int lane = threadIdx.x & 31;

    if (gw == 0 && lane == 0)
        out[OFF_LOSS] = 1.25f * g_loss / 8388608.0f;

    if (gw >= HH * MM) return;
    int h = gw >> 10;
    int m = gw & (MM - 1);

    const float* hi = cb + ((size_t)h * MM + m) * DD;
    float h0 = hi[lane], h1 = hi[lane + 32];
    float cnt = g_counts[h * MM + m];
    float o0 = h0, o1 = h1;

    if (cnt > 0.0f) {
        float inv = 1.0f / fmaxf(cnt, 1.0f);
        const float* sp = g_sums + ((size_t)h * MM + m) * DD;
        float s0 = sp[lane] * inv, s1 = sp[lane + 32] * inv;

        float dot = s0 * h0 + s1 * h1;
        float nl = s0 * s0 + s1 * s1;
        float nh = h0 * h0 + h1 * h1;
#pragma unroll
        for (int off = 16; off > 0; off >>= 1) {
            dot += __shfl_xor_sync(0xFFFFFFFFu, dot, off);
            nl  += __shfl_xor_sync(0xFFFFFFFFu, nl, off);
            nh  += __shfl_xor_sync(0xFFFFFFFFu, nh, off);
        }
        float c = dot / fmaxf(sqrtf(nl) * sqrtf(nh), COS_EPS);
        c = fminf(fmaxf(c, -1.0f + 1e-7f), 1.0f - 1e-7f);
        float om = acosf(c);
        float so = sinf(om);
        float wl = sinf(0.01f * om) / so;
        float wh = sinf(0.99f * om) / so;
        float r0 = s0 * wl + h0 * wh;
        float r1 = s1 * wl + h1 * wh;

        float ms = r0 * r0 + r1 * r1;
#pragma unroll
        for (int off = 16; off > 0; off >>= 1)
            ms += __shfl_xor_sync(0xFFFFFFFFu, ms, off);
        float rinv = rsqrtf(ms * (1.0f / 64.0f) + RMS_EPS);
        o0 = r0 * rinv;
        o1 = r1 * rinv;
    }

    size_t ob = OFF_CB + ((size_t)h * MM + m) * DD;
    out[ob + lane] = o0;
    out[ob + lane + 32] = o1;
}

// ---------------------------------------------------------------------------
extern "C" void kernel_launch(void* const* d_in, const int* in_sizes, int n_in,
                              void* d_out, int out_size) {
    const float* z  = (const float*)d_in[0];
    const float* cb = (const float*)d_in[1];
    float* out = (float*)d_out;

    cudaFuncSetAttribute(vq_gemm, cudaFuncAttributeMaxDynamicSharedMemorySize,
                         SM_GEMM);

    vq_prep<<<4096, 256>>>(z, cb);
    vq_gemm<<<dim3(128, 8), 256, SM_GEMM>>>(out);
    vq_epi<<<dim3(32, 8, 8), 256>>>(z, cb, out);
    vq_update<<<1024, 256>>>(cb, out);
}

// round 4
// speedup vs baseline: 3.9839x; 1.5877x over previous
#include <cuda_runtime.h>
#include <cuda_bf16.h>
#include <math.h>
#include <cstdint>

// ---------------- problem constants ----------------
#define HH 8
#define BB 8
#define LL 2048
#define MM 1024
#define DD 64
#define NPH 16384                         // tokens per head = BB*LL

// output layout (fp32, reference return order)
#define OFF_ZQ   0
#define N_ZQ     (8*512*2048)             // 8,388,608
#define OFF_LOSS (N_ZQ)
#define OFF_IDX  (N_ZQ + 1)
#define OFF_CB   (OFF_IDX + BB*HH*LL)

#define RMS_EPS  1.1920929e-07f
#define COS_EPS  1e-8f

// ---------------- device scratch (no allocs) ----------------
__device__ __align__(128) __nv_bfloat16 g_c1[HH*MM*DD];
__device__ __align__(128) __nv_bfloat16 g_c2[HH*MM*DD];
__device__ __align__(128) __nv_bfloat16 g_c3[HH*MM*DD];
__device__ __align__(16) float g_sums[HH*MM*DD];
__device__ float g_counts[HH*MM];
__device__ float g_loss;

// ---------------- mma / ldmatrix helpers ----------------
__device__ __forceinline__ void mma_bf16(float* d, const uint32_t* a,
                                         const uint32_t* b) {
    asm volatile(
        "mma.sync.aligned.m16n8k16.row.col.f32.bf16.bf16.f32 "
        "{%0,%1,%2,%3}, {%4,%5,%6,%7}, {%8,%9}, {%0,%1,%2,%3};"
        : "+f"(d[0]), "+f"(d[1]), "+f"(d[2]), "+f"(d[3])
        : "r"(a[0]), "r"(a[1]), "r"(a[2]), "r"(a[3]), "r"(b[0]), "r"(b[1]));
}
__device__ __forceinline__ void ldsm_x4(uint32_t& r0, uint32_t& r1,
                                        uint32_t& r2, uint32_t& r3,
                                        uint32_t addr) {
    asm volatile("ldmatrix.sync.aligned.m8n8.x4.shared.b16 {%0,%1,%2,%3}, [%4];"
                 : "=r"(r0), "=r"(r1), "=r"(r2), "=r"(r3) : "r"(addr));
}
__device__ __forceinline__ uint32_t smem_u32(const void* p) {
    uint32_t a;
    asm("{ .reg .u64 t; cvta.to.shared.u64 t, %1; cvt.u32.u64 %0, t; }"
        : "=r"(a) : "l"(p));
    return a;
}

// ---------------- split fp32 -> 3 bf16 terms ----------------
__device__ __forceinline__ void split3(float v, __nv_bfloat16& a, __nv_bfloat16& b,
                                       __nv_bfloat16& c) {
    a = __float2bfloat16(v);
    float r = v - __bfloat162float(a);
    b = __float2bfloat16(r);
    float r2 = r - __bfloat162float(b);
    c = __float2bfloat16(r2);
}
__device__ __forceinline__ uint32_t pack2(__nv_bfloat16 lo, __nv_bfloat16 hi) {
    __nv_bfloat162 t;
    t.x = lo; t.y = hi;
    return *(uint32_t*)&t;
}

// ---------------------------------------------------------------------------
// K0: prep — split codebooks to 3 bf16 terms; zero scratch
// ---------------------------------------------------------------------------
__global__ __launch_bounds__(256)
void vq_prep(const float* __restrict__ cb) {
    int i = blockIdx.x * 256 + threadIdx.x;   // < 524288
    float v = cb[i];
    __nv_bfloat16 a, b, c;
    split3(v, a, b, c);
    g_c1[i] = a; g_c2[i] = b; g_c3[i] = c;
    g_sums[i] = 0.0f;
    if (i < HH * MM) g_counts[i] = 0.0f;
    if (i == 0) g_loss = 0.0f;
}

// ---------------------------------------------------------------------------
// K1: fused — z stage + split + HMMA 6-pair sim-GEMM + argmax + epilogue
// CTA = (head, 128 tokens). 8 warps; warp w owns rows [w*16, w*16+16).
// ---------------------------------------------------------------------------
#define BPITCH 144
#define BTERM  (128 * BPITCH)             // 18432 B / term
#define ZPITCH 132
#define SM_B    0
#define SM_Z    (3 * BTERM)               // 55296
#define SM_SIDX (SM_Z + 64 * ZPITCH * 4)  // 89088
#define SM_WSUM (SM_SIDX + 512)           // 89600
#define SM_TOTAL (SM_WSUM + 32)           // 89632

__global__ __launch_bounds__(256)
void vq_gemm(const float* __restrict__ z, const float* __restrict__ cb,
             float* __restrict__ out) {
    extern __shared__ char smem[];
    float* zsh = (float*)(smem + SM_Z);
    int* sidx = (int*)(smem + SM_SIDX);
    float* wsum = (float*)(smem + SM_WSUM);
    const uint32_t sb = smem_u32(smem);

    const int h  = blockIdx.y;
    const int n0 = blockIdx.x * 128;
    const int b  = n0 >> 11;              // batch
    const int l0 = n0 & 2047;             // l offset within batch
    const int tid = threadIdx.x;
    const int w = tid >> 5, l = tid & 31;
    const int gq = l >> 2, tq = l & 3;

    // ---- stage z tile fp32: zsh[k][l] (64 x 128), coalesced ----
    const float* zb = z + ((size_t)b * 512 + (size_t)h * 64) * 2048 + l0;
    for (int i = tid; i < 64 * 32; i += 256) {
        int k = i >> 5, c = i & 31;
        float4 v = __ldg((const float4*)(zb + (size_t)k * 2048 + c * 4));
        *(float4*)(zsh + k * ZPITCH + c * 4) = v;
    }
    __syncthreads();

    // ---- build A fragments in regs: 3 terms x 4 ksteps x 4 regs ----
    uint32_t afr[3][4][4];
    {
        const int r0 = w * 16 + gq;
#pragma unroll
        for (int ks = 0; ks < 4; ks++)
#pragma unroll
            for (int half = 0; half < 2; half++)
#pragma unroll
                for (int rr = 0; rr < 2; rr++) {
                    int k0 = ks * 16 + 2 * tq + half * 8;
                    int row = r0 + rr * 8;
                    float v0 = zsh[k0 * ZPITCH + row];
                    float v1 = zsh[(k0 + 1) * ZPITCH + row];
                    __nv_bfloat16 a0, b0, c0, a1, b1, c1;
                    split3(v0, a0, b0, c0);
                    split3(v1, a1, b1, c1);
                    int reg = rr + half * 2;
                    afr[0][ks][reg] = pack2(a0, a1);
                    afr[1][ks][reg] = pack2(b0, b1);
                    afr[2][ks][reg] = pack2(c0, c1);
                }
    }

    float best0 = -3.0e38f, best1 = -3.0e38f;
    int   bidx0 = 0, bidx1 = 0;

    const int PA[6] = {0, 0, 1, 0, 1, 2};
    const int PB[6] = {0, 1, 0, 2, 1, 0};

    // per-lane ldmatrix row offset: g = l>>3 in [0,4), j = l&7
    const uint32_t laneoff = (((l >> 4) * 8 + (l & 7)) * BPITCH) + (((l >> 3) & 1) * 16);

    for (int mt = 0; mt < 8; mt++) {
        __syncthreads();
        // ---- stage B tile: 128 codes x 64 k x 3 terms, pitch 144B ----
#pragma unroll
        for (int t3 = 0; t3 < 3; t3++) {
            const __nv_bfloat16* cp = (t3 == 0) ? g_c1 : (t3 == 1) ? g_c2 : g_c3;
            const uint4* src = (const uint4*)(cp + ((size_t)h * MM + mt * 128) * DD);
            char* dst = smem + t3 * BTERM;
            for (int i = tid; i < 1024; i += 256) {
                int r = i >> 3, c = i & 7;
                *(uint4*)(dst + r * BPITCH + c * 16) = __ldg(src + i);
            }
        }
        __syncthreads();

#pragma unroll
        for (int sg = 0; sg < 4; sg++) {
            float acc[4][4];
#pragma unroll
            for (int s = 0; s < 4; s++)
#pragma unroll
                for (int i = 0; i < 4; i++) acc[s][i] = 0.0f;

#pragma unroll
            for (int ks = 0; ks < 4; ks++) {
                uint32_t bfr[3][4][2];
#pragma unroll
                for (int t3 = 0; t3 < 3; t3++)
#pragma unroll
                    for (int sp = 0; sp < 2; sp++) {
                        uint32_t addr = sb + t3 * BTERM +
                                        (sg * 32 + sp * 16) * BPITCH +
                                        ks * 32 + laneoff;
                        ldsm_x4(bfr[t3][sp * 2][0], bfr[t3][sp * 2][1],
                                bfr[t3][sp * 2 + 1][0], bfr[t3][sp * 2 + 1][1],
                                addr);
                    }
#pragma unroll
                for (int p6 = 0; p6 < 6; p6++)
#pragma unroll
                    for (int s = 0; s < 4; s++)
                        mma_bf16(acc[s], afr[PA[p6]][ks], bfr[PB[p6]][s]);
            }

            // argmax update (ascending scan, strict > keeps lowest index)
#pragma unroll
            for (int s = 0; s < 4; s++) {
                int nb = mt * 128 + sg * 32 + s * 8 + 2 * tq;
                if (acc[s][0] > best0) { best0 = acc[s][0]; bidx0 = nb; }
                if (acc[s][1] > best0) { best0 = acc[s][1]; bidx0 = nb + 1; }
                if (acc[s][2] > best1) { best1 = acc[s][2]; bidx1 = nb; }
                if (acc[s][3] > best1) { best1 = acc[s][3]; bidx1 = nb + 1; }
            }
        }
    }

    // ---- reduce argmax across the 4 lanes covering each row ----
#pragma unroll
    for (int off = 1; off <= 2; off <<= 1) {
        float ov = __shfl_xor_sync(0xFFFFFFFFu, best0, off);
        int   oi = __shfl_xor_sync(0xFFFFFFFFu, bidx0, off);
        if (ov > best0 || (ov == best0 && oi < bidx0)) { best0 = ov; bidx0 = oi; }
        ov = __shfl_xor_sync(0xFFFFFFFFu, best1, off);
        oi = __shfl_xor_sync(0xFFFFFFFFu, bidx1, off);
        if (ov > best1 || (ov == best1 && oi < bidx1)) { best1 = ov; bidx1 = oi; }
    }

    if (tq == 0) {
        int rl = w * 16 + gq;
        sidx[rl] = bidx0;
        sidx[rl + 8] = bidx1;
        out[OFF_IDX + ((size_t)(b * HH + h)) * LL + l0 + rl] = (float)bidx0;
        out[OFF_IDX + ((size_t)(b * HH + h)) * LL + l0 + rl + 8] = (float)bidx1;
        atomicAdd(&g_counts[h * MM + bidx0], 1.0f);
        atomicAdd(&g_counts[h * MM + bidx1], 1.0f);
    }
    __syncthreads();

    // ---- fused epilogue: z_q write, loss, segment sums ----
    const float* cbh = cb + (size_t)h * MM * DD;
    float* zqb = out + OFF_ZQ + ((size_t)b * 512 + (size_t)h * 64) * 2048 + l0;
    float lsum = 0.0f;
    for (int i = tid; i < 64 * 128; i += 256) {
        int k = i >> 7, ll = i & 127;
        int m = sidx[ll];
        float cv = __ldg(&cbh[(size_t)m * DD + k]);
        float zv = zsh[k * ZPITCH + ll];
        float d = zv - cv;
        lsum += d * d;
        zqb[(size_t)k * 2048 + ll] = cv;
    }

    // segment sums: thread = (l, 4k-group) -> float4 atomic
    for (int i = tid; i < 128 * 16; i += 256) {
        int ll = i >> 4, kg = i & 15;
        int m = sidx[ll];
        float4 v = make_float4(zsh[(4 * kg) * ZPITCH + ll],
                               zsh[(4 * kg + 1) * ZPITCH + ll],
                               zsh[(4 * kg + 2) * ZPITCH + ll],
                               zsh[(4 * kg + 3) * ZPITCH + ll]);
        atomicAdd((float4*)&g_sums[((size_t)(h * MM + m)) * DD + 4 * kg], v);
    }

    // loss reduce
#pragma unroll
    for (int off = 16; off > 0; off >>= 1)
        lsum += __shfl_xor_sync(0xFFFFFFFFu, lsum, off);
    if (l == 0) wsum[w] = lsum;
    __syncthreads();
    if (tid == 0) {
        float s = 0.0f;
#pragma unroll
        for (int ww = 0; ww < 8; ww++) s += wsum[ww];
        atomicAdd(&g_loss, s);
    }
}

// ---------------------------------------------------------------------------
// K2: EMA slerp codebook update + loss finalize. One warp per (h, m).
// ---------------------------------------------------------------------------
__global__ __launch_bounds__(256)
void vq_update(const float* __restrict__ cb, float* __restrict__ out) {
    int gid = blockIdx.x * blockDim.x + threadIdx.x;
    int gw = gid >> 5;
    int lane = threadIdx.x & 31;

    if (gw == 0 && lane == 0)
        out[OFF_LOSS] = 1.25f * g_loss / 8388608.0f;

    if (gw >= HH * MM) return;
    int h = gw >> 10;
    int m = gw & (MM - 1);

    const float* hi = cb + ((size_t)h * MM + m) * DD;
    float h0 = hi[lane], h1 = hi[lane + 32];
    float cnt = g_counts[h * MM + m];
    float o0 = h0, o1 = h1;

    if (cnt > 0.0f) {
        float inv = 1.0f / fmaxf(cnt, 1.0f);
        const float* sp = g_sums + ((size_t)h * MM + m) * DD;
        float s0 = sp[lane] * inv, s1 = sp[lane + 32] * inv;

        float dot = s0 * h0 + s1 * h1;
        float nl = s0 * s0 + s1 * s1;
        float nh = h0 * h0 + h1 * h1;
#pragma unroll
        for (int off = 16; off > 0; off >>= 1) {
            dot += __shfl_xor_sync(0xFFFFFFFFu, dot, off);
            nl  += __shfl_xor_sync(0xFFFFFFFFu, nl, off);
            nh  += __shfl_xor_sync(0xFFFFFFFFu, nh, off);
        }
        float c = dot / fmaxf(sqrtf(nl) * sqrtf(nh), COS_EPS);
        c = fminf(fmaxf(c, -1.0f + 1e-7f), 1.0f - 1e-7f);
        float om = acosf(c);
        float so = sinf(om);
        float wl = sinf(0.01f * om) / so;
        float wh = sinf(0.99f * om) / so;
        float r0 = s0 * wl + h0 * wh;
        float r1 = s1 * wl + h1 * wh;

        float ms = r0 * r0 + r1 * r1;
#pragma unroll
        for (int off = 16; off > 0; off >>= 1)
            ms += __shfl_xor_sync(0xFFFFFFFFu, ms, off);
        float rinv = rsqrtf(ms * (1.0f / 64.0f) + RMS_EPS);
        o0 = r0 * rinv;
        o1 = r1 * rinv;
    }

    size_t ob = OFF_CB + ((size_t)h * MM + m) * DD;
    out[ob + lane] = o0;
    out[ob + lane + 32] = o1;
}

// ---------------------------------------------------------------------------
extern "C" void kernel_launch(void* const* d_in, const int* in_sizes, int n_in,
                              void* d_out, int out_size) {
    const float* z  = (const float*)d_in[0];
    const float* cb = (const float*)d_in[1];
    float* out = (float*)d_out;

    cudaFuncSetAttribute(vq_gemm, cudaFuncAttributeMaxDynamicSharedMemorySize,
                         SM_TOTAL);

    vq_prep<<<2048, 256>>>(cb);
    vq_gemm<<<dim3(128, 8), 256, SM_TOTAL>>>(z, cb, out);
    vq_update<<<1024, 256>>>(cb, out);
}